// round 4
// baseline (speedup 1.0000x reference)
#include <cuda_runtime.h>
#include <cstddef>

#define BS      2048
#define NN      8
#define GPB     7                 // graphs per block
#define MROWS   (GPB*NN)          // 56 rows per block
#define NBLK    ((BS + GPB - 1) / GPB)   // 293
#define NSTEPS  8
#define THREADS 256

// dynamic smem: h[56][128] + AB[56][256] + wtile[4096]
#define SMEM_FLOATS (MROWS*128 + MROWS*256 + 4096)
#define SMEM_BYTES  (SMEM_FLOATS * 4)

typedef unsigned long long u64;

// scratch (allocation-free rule: __device__ globals)
__device__ float g_Wsn[128 * 128];      // msg_w2 @ node_w1[256:384]
__device__ float g_biasN[128];          // node_b1 + 7 * msg_b2 @ node_w1[256:384]
__device__ float g_x[BS * NN * 128];    // pre-MLP output (step-invariant)

// ---- packed fp32x2 helpers (FFMA2: 2 FMAs / instruction on sm_103a) ----
__device__ __forceinline__ void fma2(u64& d, u64 a, u64 b) {
    asm("fma.rn.f32x2 %0, %1, %2, %0;" : "+l"(d) : "l"(a), "l"(b));
}
__device__ __forceinline__ u64 pack2(float x, float y) {
    u64 r; asm("mov.b64 %0, {%1, %2};" : "=l"(r) : "f"(x), "f"(y)); return r;
}
__device__ __forceinline__ float2 unpack2(u64 v) {
    float2 f; asm("mov.b64 {%0, %1}, %2;" : "=f"(f.x), "=f"(f.y) : "l"(v)); return f;
}

// ---------------------------------------------------------------------------
// Fold msg second layer into node first layer (weights are step-invariant).
// ---------------------------------------------------------------------------
__global__ void precompute_kernel(const float* __restrict__ msg_w2,
                                  const float* __restrict__ msg_b2,
                                  const float* __restrict__ node_w1,
                                  const float* __restrict__ node_b1)
{
    int a = blockIdx.x;   // 0..127
    int c = threadIdx.x;  // 0..127
    float acc = 0.f;
#pragma unroll 8
    for (int r = 0; r < 128; ++r)
        acc = fmaf(msg_w2[a * 128 + r], node_w1[(256 + r) * 128 + c], acc);
    g_Wsn[a * 128 + c] = acc;
    if (a == 0) {
        float b = 0.f;
#pragma unroll 8
        for (int r = 0; r < 128; ++r)
            b = fmaf(msg_b2[r], node_w1[(256 + r) * 128 + c], b);
        g_biasN[c] = node_b1[c] + 7.f * b;
    }
}

// ---------------------------------------------------------------------------
// Tiled smem GEMM with packed f32x2 accumulation:
//   acc[7][NC2] (each a float pair) += act[56 x 128] @ W[128 x (NC2*64)]
// Thread (ty,tx): rows ty+8i, column pairs c = 2*tx + 64*j (+0/1).
// b-frags: LDS.64 contiguous per warp; a-frags: LDS.64 broadcast (2 k's).
// Unroll capped at 4 kk-pairs to keep each loop body L0-I$-resident.
// ---------------------------------------------------------------------------
template <int NC2, int KT>
__device__ __forceinline__ void gemm2(u64 (&acc)[7][NC2],
                                      const float* __restrict__ actBase,
                                      int actStride,
                                      float* __restrict__ sh_w,
                                      const float* __restrict__ W,
                                      int kOff, int tid, int ty, int tx)
{
    constexpr int WN = NC2 * 64;
    for (int k0 = 0; k0 < 128; k0 += KT) {
        __syncthreads();   // previous tile / previous phase fully consumed
        for (int e = tid; e < KT * WN / 4; e += THREADS) {
            int idx = e * 4;
            int kk = idx / WN, c = idx % WN;
            *(float4*)&sh_w[idx] = *(const float4*)&W[(kOff + k0 + kk) * 128 + c];
        }
        __syncthreads();
        const float* act = actBase + k0;
#pragma unroll 4
        for (int kk0 = 0; kk0 < KT; kk0 += 2) {
            float2 a2[7];
#pragma unroll
            for (int i = 0; i < 7; ++i)
                a2[i] = *(const float2*)&act[(ty + 8 * i) * actStride + kk0];
            u64 b0[NC2], b1[NC2];
#pragma unroll
            for (int j = 0; j < NC2; ++j) {
                b0[j] = *(const u64*)&sh_w[kk0 * WN + 2 * tx + 64 * j];
                b1[j] = *(const u64*)&sh_w[(kk0 + 1) * WN + 2 * tx + 64 * j];
            }
#pragma unroll
            for (int i = 0; i < 7; ++i) {
                u64 ax = pack2(a2[i].x, a2[i].x);
#pragma unroll
                for (int j = 0; j < NC2; ++j) fma2(acc[i][j], ax, b0[j]);
            }
#pragma unroll
            for (int i = 0; i < 7; ++i) {
                u64 ay = pack2(a2[i].y, a2[i].y);
#pragma unroll
                for (int j = 0; j < NC2; ++j) fma2(acc[i][j], ay, b1[j]);
            }
        }
    }
}

// ---------------------------------------------------------------------------
// One block = 7 graphs, runs the entire 8-step recurrence block-locally.
// ---------------------------------------------------------------------------
__global__ void __launch_bounds__(THREADS, 2)
rrn_kernel(const int* __restrict__ sources, const int* __restrict__ targets,
           const int* __restrict__ types, const int* __restrict__ diffs,
           const int* __restrict__ question,
           const float* __restrict__ pre_w1, const float* __restrict__ pre_b1,
           const float* __restrict__ pre_w2, const float* __restrict__ pre_b2,
           const float* __restrict__ msg_w1, const float* __restrict__ msg_b1,
           const float* __restrict__ node_w1, const float* __restrict__ node_w2,
           const float* __restrict__ node_b2,
           const float* __restrict__ out_w1, const float* __restrict__ out_b1,
           const float* __restrict__ out_w2, const float* __restrict__ out_b2,
           float* __restrict__ out)
{
    extern __shared__ float smem[];
    float* sh_h  = smem;                          // 56 x 128  (h, persists across steps)
    float* sh_AB = smem + MROWS * 128;            // 56 x 256  (A|B, then S|hidden, then x|hidden)
    float* sh_w  = smem + MROWS * 128 + MROWS * 256;  // 4096 floats (weight tiles / pooled / ohid)

    __shared__ float s_msgb1[128], s_biasN[128], s_nb2[128], s_pb2[128];

    const int tid = threadIdx.x;
    const int tx = tid & 31, ty = tid >> 5;
    const int nodeBase  = blockIdx.x * MROWS;
    const int graphBase = blockIdx.x * GPB;

    if (tid < 128) {
        s_msgb1[tid] = msg_b1[tid];
        s_biasN[tid] = g_biasN[tid];
        s_nb2[tid]   = node_b2[tid];
        s_pb2[tid]   = pre_b2[tid];
    }

    // ---- pre-MLP: hidden = relu(one-hot gather of pre_w1 rows + b1) ----
    for (int e = tid; e < MROWS * 128; e += THREADS) {
        int r = e >> 7, c = e & 127;
        int n = nodeBase + r;
        float v = 0.f;
        if (n < BS * NN) {
            int g  = n >> 3;
            int s  = sources[n], t = targets[n], tp = types[n], d = diffs[n];
            int q  = question[g];
            v = pre_w1[s * 128 + c] + pre_w1[(8 + t) * 128 + c]
              + pre_w1[(16 + tp) * 128 + c] + pre_w1[(19 + d) * 128 + c]
              + pre_w1[(119 + q) * 128 + c] + pre_b1[c];
            v = fmaxf(v, 0.f);
        }
        sh_AB[r * 256 + c] = v;
    }
    // x = hidden @ pre_w2 + pre_b2 ; h0 = x ; stash x to global (re-staged per step)
    {
        u64 acc[7][2] = {};
        gemm2<2, 32>(acc, sh_AB, 256, sh_w, pre_w2, 0, tid, ty, tx);
#pragma unroll
        for (int i = 0; i < 7; ++i)
#pragma unroll
            for (int j = 0; j < 2; ++j) {
                int r = ty + 8 * i, c = 2 * tx + 64 * j;
                float2 v = unpack2(acc[i][j]);
                v.x += s_pb2[c]; v.y += s_pb2[c + 1];
                *(float2*)&sh_h[r * 128 + c] = v;
                int n = nodeBase + r;
                if (n < BS * NN) *(float2*)&g_x[n * 128 + c] = v;
            }
    }

    for (int step = 0; step < NSTEPS; ++step) {
        // ---- Phase 1: [A|B] = h @ [msg_w1[0:128] | msg_w1[128:256]] (WN=256) ----
        {
            u64 acc[7][4] = {};
            for (int k0 = 0; k0 < 128; k0 += 16) {
                __syncthreads();
                for (int e = tid; e < 16 * 256 / 4; e += THREADS) {
                    int idx = e * 4;
                    int kk = idx >> 8, c = idx & 255;
                    int k = k0 + kk;
                    *(float4*)&sh_w[idx] =
                        (c < 128) ? *(const float4*)&msg_w1[k * 128 + c]
                                  : *(const float4*)&msg_w1[(128 + k) * 128 + (c - 128)];
                }
                __syncthreads();
                const float* act = sh_h + k0;
#pragma unroll 4
                for (int kk0 = 0; kk0 < 16; kk0 += 2) {
                    float2 a2[7];
#pragma unroll
                    for (int i = 0; i < 7; ++i)
                        a2[i] = *(const float2*)&act[(ty + 8 * i) * 128 + kk0];
                    u64 b0[4], b1[4];
#pragma unroll
                    for (int j = 0; j < 4; ++j) {
                        b0[j] = *(const u64*)&sh_w[kk0 * 256 + 2 * tx + 64 * j];
                        b1[j] = *(const u64*)&sh_w[(kk0 + 1) * 256 + 2 * tx + 64 * j];
                    }
#pragma unroll
                    for (int i = 0; i < 7; ++i) {
                        u64 ax = pack2(a2[i].x, a2[i].x);
#pragma unroll
                        for (int j = 0; j < 4; ++j) fma2(acc[i][j], ax, b0[j]);
                    }
#pragma unroll
                    for (int i = 0; i < 7; ++i) {
                        u64 ay = pack2(a2[i].y, a2[i].y);
#pragma unroll
                        for (int j = 0; j < 4; ++j) fma2(acc[i][j], ay, b1[j]);
                    }
                }
            }
#pragma unroll
            for (int i = 0; i < 7; ++i)
#pragma unroll
                for (int j = 0; j < 4; ++j)
                    *(float2*)&sh_AB[(ty + 8 * i) * 256 + 2 * tx + 64 * j] = unpack2(acc[i][j]);
        }

        // ---- Phase 2: S[i] = sum_{j != i, same graph} relu(A[i]+B[j]+b1), in place over A
        __syncthreads();
        for (int e = tid; e < MROWS * 64; e += THREADS) {
            int r = e >> 6, c = (e & 63) * 2;
            int gl8 = r & ~7;  // local graph row base
            float2 a = *(const float2*)&sh_AB[r * 256 + c];
            a.x += s_msgb1[c]; a.y += s_msgb1[c + 1];
            float sx = 0.f, sy = 0.f;
#pragma unroll
            for (int j = 0; j < 8; ++j) {
                float2 b = *(const float2*)&sh_AB[(gl8 + j) * 256 + 128 + c];
                sx += fmaxf(a.x + b.x, 0.f);
                sy += fmaxf(a.y + b.y, 0.f);
            }
            {   // remove j == i term
                float2 b = *(const float2*)&sh_AB[r * 256 + 128 + c];
                sx -= fmaxf(a.x + b.x, 0.f);
                sy -= fmaxf(a.y + b.y, 0.f);
            }
            float2 s2 = make_float2(sx, sy);
            *(float2*)&sh_AB[r * 256 + c] = s2;
        }

        // ---- Phase 3: hidden = relu(S@Wsn + x@node_w1[0:128] + h@node_w1[128:256] + biasN)
        {
            u64 acc[7][2] = {};
            gemm2<2, 32>(acc, sh_AB, 256, sh_w, g_Wsn, 0, tid, ty, tx);   // S segment
            __syncthreads();  // all S reads done -> overwrite A region with x
            for (int e = tid; e < MROWS * 64; e += THREADS) {
                int r = e >> 6, c = (e & 63) * 2;
                int n = nodeBase + r;
                float2 v = make_float2(0.f, 0.f);
                if (n < BS * NN) v = *(const float2*)&g_x[n * 128 + c];
                *(float2*)&sh_AB[r * 256 + c] = v;
            }
            gemm2<2, 32>(acc, sh_AB, 256, sh_w, node_w1, 0,   tid, ty, tx);  // x segment
            gemm2<2, 32>(acc, sh_h,  128, sh_w, node_w1, 128, tid, ty, tx);  // h segment
#pragma unroll
            for (int i = 0; i < 7; ++i)
#pragma unroll
                for (int j = 0; j < 2; ++j) {
                    int c = 2 * tx + 64 * j;
                    float2 v = unpack2(acc[i][j]);
                    v.x = fmaxf(v.x + s_biasN[c], 0.f);
                    v.y = fmaxf(v.y + s_biasN[c + 1], 0.f);
                    *(float2*)&sh_AB[(ty + 8 * i) * 256 + 128 + c] = v;
                }
        }

        // ---- Phase 4: h_new = hidden @ node_w2 + node_b2 (overwrites h) ----
        {
            u64 acc[7][2] = {};
            gemm2<2, 32>(acc, sh_AB + 128, 256, sh_w, node_w2, 0, tid, ty, tx);
#pragma unroll
            for (int i = 0; i < 7; ++i)
#pragma unroll
                for (int j = 0; j < 2; ++j) {
                    int c = 2 * tx + 64 * j;
                    float2 v = unpack2(acc[i][j]);
                    v.x += s_nb2[c]; v.y += s_nb2[c + 1];
                    *(float2*)&sh_h[(ty + 8 * i) * 128 + c] = v;
                }
        }

        // ---- Phase 5: per-graph pool + out MLP -> logits[step] ----
        __syncthreads();
        float* pooled = sh_w;          // GPB*128 = 896
        float* ohid   = sh_w + 1024;   // GPB*128
        for (int e = tid; e < GPB * 128; e += THREADS) {
            int g = e >> 7, c = e & 127;
            float s = 0.f;
#pragma unroll
            for (int i = 0; i < 8; ++i) s += sh_h[(g * 8 + i) * 128 + c];
            pooled[e] = s;
        }
        __syncthreads();
        for (int e = tid; e < GPB * 128; e += THREADS) {
            int g = e >> 7, c = e & 127;
            float s = out_b1[c];
#pragma unroll 8
            for (int k = 0; k < 128; ++k)
                s = fmaf(pooled[g * 128 + k], out_w1[k * 128 + c], s);
            ohid[e] = fmaxf(s, 0.f);
        }
        __syncthreads();
        for (int e = tid; e < GPB * 100; e += THREADS) {
            int g = e / 100, c = e - g * 100;
            int gg = graphBase + g;
            if (gg < BS) {
                float s = out_b2[c];
#pragma unroll 8
                for (int k = 0; k < 128; ++k)
                    s = fmaf(ohid[g * 128 + k], out_w2[k * 100 + c], s);
                out[((size_t)step * BS + gg) * 100 + c] = s;
            }
        }
        // next phase-1's leading __syncthreads covers sh_w reuse
    }
}

extern "C" void kernel_launch(void* const* d_in, const int* in_sizes, int n_in,
                              void* d_out, int out_size)
{
    (void)in_sizes; (void)n_in; (void)out_size;
    const int*   sources  = (const int*)d_in[0];
    const int*   targets  = (const int*)d_in[1];
    const int*   types    = (const int*)d_in[2];
    const int*   diffs    = (const int*)d_in[3];
    const int*   question = (const int*)d_in[4];
    const float* pre_w1   = (const float*)d_in[5];
    const float* pre_b1   = (const float*)d_in[6];
    const float* pre_w2   = (const float*)d_in[7];
    const float* pre_b2   = (const float*)d_in[8];
    const float* msg_w1   = (const float*)d_in[9];
    const float* msg_b1   = (const float*)d_in[10];
    const float* msg_w2   = (const float*)d_in[11];
    const float* msg_b2   = (const float*)d_in[12];
    const float* node_w1  = (const float*)d_in[13];
    const float* node_b1  = (const float*)d_in[14];
    const float* node_w2  = (const float*)d_in[15];
    const float* node_b2  = (const float*)d_in[16];
    const float* out_w1   = (const float*)d_in[17];
    const float* out_b1   = (const float*)d_in[18];
    const float* out_w2   = (const float*)d_in[19];
    const float* out_b2   = (const float*)d_in[20];
    float* out = (float*)d_out;

    cudaFuncSetAttribute(rrn_kernel, cudaFuncAttributeMaxDynamicSharedMemorySize,
                         SMEM_BYTES);

    precompute_kernel<<<128, 128>>>(msg_w2, msg_b2, node_w1, node_b1);
    rrn_kernel<<<NBLK, THREADS, SMEM_BYTES>>>(
        sources, targets, types, diffs, question,
        pre_w1, pre_b1, pre_w2, pre_b2,
        msg_w1, msg_b1, node_w1, node_w2, node_b2,
        out_w1, out_b1, out_w2, out_b2, out);
}

// round 13
// speedup vs baseline: 1.7316x; 1.7316x over previous
#include <cuda_runtime.h>
#include <cstddef>

#define BS      2048
#define NN      8
#define GPB     7                 // graphs per block
#define MROWS   (GPB*NN)          // 56 rows per block
#define NBLK    ((BS + GPB - 1) / GPB)   // 293
#define NSTEPS  8
#define THREADS 256

// dynamic smem: hid[56][128] + AB[56][256] + wtile[4096]
#define SMEM_FLOATS (MROWS*128 + MROWS*256 + 4096)
#define SMEM_BYTES  (SMEM_FLOATS * 4)

typedef unsigned long long u64;

// ---- folded weights / biases (device-global scratch; allocation-free) ----
__device__ float g_WfA[128 * 128];      // node_w2 @ msg_w1[0:128]
__device__ float g_WfB[128 * 128];      // node_w2 @ msg_w1[128:256]
__device__ float g_W3[256 * 128];       // [ msg_w2@node_w1[256:384] ; node_w2@node_w1[128:256] ]
__device__ float g_Wsum[128 * 128];     // node_w1[0:128] + node_w1[128:256]
__device__ float g_Wpo[128 * 128];      // node_w2 @ out_w1
__device__ float g_cb1[128];            // msg_b1 + b2@msg_w1[0:128] + b2@msg_w1[128:256]
__device__ float g_bn0[128];            // node_b1 + 7*(msg_b2@node_w1[256:384])
__device__ float g_bn1[128];            // g_bn0 + b2@node_w1[128:256]
__device__ float g_bpo[128];            // out_b1 + 8*(b2@out_w1)
__device__ float g_xc0[NBLK * MROWS * 128];  // x@(W1x+W1h) + bn0  (step 0)
__device__ float g_xc1[NBLK * MROWS * 128];  // x@W1x + bn1        (steps >= 1)

// ---- packed fp32x2 helpers (FFMA2: 2 FMAs / instruction on sm_103a) ----
__device__ __forceinline__ void fma2(u64& d, u64 a, u64 b) {
    asm("fma.rn.f32x2 %0, %1, %2, %0;" : "+l"(d) : "l"(a), "l"(b));
}
__device__ __forceinline__ u64 pack2(float x, float y) {
    u64 r; asm("mov.b64 %0, {%1, %2};" : "=l"(r) : "f"(x), "f"(y)); return r;
}
__device__ __forceinline__ float2 unpack2(u64 v) {
    float2 f; asm("mov.b64 {%0, %1}, %2;" : "=f"(f.x), "=f"(f.y) : "l"(v)); return f;
}

// ---------------------------------------------------------------------------
// One-time weight folding (graph-captured; trivial cost).
// ---------------------------------------------------------------------------
__global__ void fold_w(const float* __restrict__ mw1, const float* __restrict__ mw2,
                       const float* __restrict__ nw1, const float* __restrict__ nw2,
                       const float* __restrict__ ow1)
{
    int r = blockIdx.x, c = threadIdx.x, y = blockIdx.y;
    float acc = 0.f;
    switch (y) {
    case 0:
#pragma unroll 8
        for (int k = 0; k < 128; ++k) acc = fmaf(nw2[r*128+k], mw1[k*128+c], acc);
        g_WfA[r*128+c] = acc; break;
    case 1:
#pragma unroll 8
        for (int k = 0; k < 128; ++k) acc = fmaf(nw2[r*128+k], mw1[(128+k)*128+c], acc);
        g_WfB[r*128+c] = acc; break;
    case 2:
#pragma unroll 8
        for (int k = 0; k < 128; ++k) acc = fmaf(mw2[r*128+k], nw1[(256+k)*128+c], acc);
        g_W3[r*128+c] = acc; break;
    case 3:
#pragma unroll 8
        for (int k = 0; k < 128; ++k) acc = fmaf(nw2[r*128+k], nw1[(128+k)*128+c], acc);
        g_W3[(128+r)*128+c] = acc; break;
    case 4:
        g_Wsum[r*128+c] = nw1[r*128+c] + nw1[(128+r)*128+c]; break;
    case 5:
#pragma unroll 8
        for (int k = 0; k < 128; ++k) acc = fmaf(nw2[r*128+k], ow1[k*128+c], acc);
        g_Wpo[r*128+c] = acc; break;
    }
}

__global__ void fold_b(const float* __restrict__ mw1, const float* __restrict__ msg_b1,
                       const float* __restrict__ msg_b2, const float* __restrict__ nw1,
                       const float* __restrict__ node_b1, const float* __restrict__ node_b2,
                       const float* __restrict__ ow1, const float* __restrict__ out_b1)
{
    int c = threadIdx.x;
    float bA = 0.f, bB = 0.f, bm = 0.f, bh = 0.f, bp = 0.f;
#pragma unroll 8
    for (int k = 0; k < 128; ++k) {
        bA = fmaf(node_b2[k], mw1[k*128+c], bA);
        bB = fmaf(node_b2[k], mw1[(128+k)*128+c], bB);
        bm = fmaf(msg_b2[k],  nw1[(256+k)*128+c], bm);
        bh = fmaf(node_b2[k], nw1[(128+k)*128+c], bh);
        bp = fmaf(node_b2[k], ow1[k*128+c], bp);
    }
    g_cb1[c] = msg_b1[c] + bA + bB;
    g_bn0[c] = node_b1[c] + 7.f * bm;
    g_bn1[c] = node_b1[c] + 7.f * bm + bh;
    g_bpo[c] = out_b1[c] + 8.f * bp;
}

// ---------------------------------------------------------------------------
// Pipelined N=128 GEMM: acc[7][2] += act[56 x (KTILES*32)] @ W[(KTILES*32) x 128]
// Weight tiles (32x128 = 16KB) staged via register prefetch: next tile's LDGs
// issue before current tile's compute, hiding L2 latency. Tiles with k>=128
// read activations from act1 (P3's [S | hid] concatenated-K trick).
// ---------------------------------------------------------------------------
template <int KTILES>
__device__ __forceinline__ void gemmP(u64 (&acc)[7][2],
                                      const float* act0, int st0,
                                      const float* act1, int st1,
                                      const float* __restrict__ W,
                                      float* __restrict__ sh_w,
                                      int tid, int ty, int tx)
{
    float4 r[4];
    {
        const float* src = W + tid * 4;
#pragma unroll
        for (int q = 0; q < 4; ++q) r[q] = *(const float4*)(src + q * 1024);
    }
#pragma unroll
    for (int t = 0; t < KTILES; ++t) {
        __syncthreads();   // all consumers done with sh_w
#pragma unroll
        for (int q = 0; q < 4; ++q)
            *(float4*)&sh_w[(tid + q * 256) * 4] = r[q];
        if (t + 1 < KTILES) {
            const float* src = W + (t + 1) * 4096 + tid * 4;
#pragma unroll
            for (int q = 0; q < 4; ++q) r[q] = *(const float4*)(src + q * 1024);
        }
        __syncthreads();   // tile visible
        const float* act; int as;
        if (t * 32 < 128) { act = act0 + t * 32;         as = st0; }
        else              { act = act1 + (t * 32 - 128); as = st1; }
#pragma unroll 4
        for (int kk0 = 0; kk0 < 32; kk0 += 2) {
            float2 a2[7];
#pragma unroll
            for (int i = 0; i < 7; ++i)
                a2[i] = *(const float2*)&act[(ty + 8 * i) * as + kk0];
            u64 b0[2], b1[2];
#pragma unroll
            for (int j = 0; j < 2; ++j) {
                b0[j] = *(const u64*)&sh_w[kk0 * 128 + 2 * tx + 64 * j];
                b1[j] = *(const u64*)&sh_w[(kk0 + 1) * 128 + 2 * tx + 64 * j];
            }
#pragma unroll
            for (int i = 0; i < 7; ++i) {
                u64 ax = pack2(a2[i].x, a2[i].x);
                fma2(acc[i][0], ax, b0[0]);
                fma2(acc[i][1], ax, b0[1]);
            }
#pragma unroll
            for (int i = 0; i < 7; ++i) {
                u64 ay = pack2(a2[i].y, a2[i].y);
                fma2(acc[i][0], ay, b1[0]);
                fma2(acc[i][1], ay, b1[1]);
            }
        }
    }
}

// ---------------------------------------------------------------------------
// One block = 7 graphs; full 8-step recurrence block-locally on state `hid`.
// ---------------------------------------------------------------------------
__global__ void __launch_bounds__(THREADS, 2)
rrn_kernel(const int* __restrict__ sources, const int* __restrict__ targets,
           const int* __restrict__ types, const int* __restrict__ diffs,
           const int* __restrict__ question,
           const float* __restrict__ pre_w1, const float* __restrict__ pre_b1,
           const float* __restrict__ pre_w2, const float* __restrict__ pre_b2,
           const float* __restrict__ msg_w1, const float* __restrict__ msg_b1,
           const float* __restrict__ node_w1,
           const float* __restrict__ out_w2, const float* __restrict__ out_b2,
           float* __restrict__ out)
{
    extern __shared__ float smem[];
    float* sh_hid = smem;                              // 56 x 128 (state)
    float* sh_AB  = smem + MROWS * 128;                // 56 x 256 (A|B then S|-)
    float* sh_w   = smem + MROWS * 128 + MROWS * 256;  // 4096 (wtile / pooled / o1)

    __shared__ float s_cb[2][128], s_pb2[128], s_bpo[128];

    const int tid = threadIdx.x;
    const int tx = tid & 31, ty = tid >> 5;
    const int nodeBase  = blockIdx.x * MROWS;
    const int graphBase = blockIdx.x * GPB;

    if (tid < 128) {
        s_cb[0][tid] = msg_b1[tid];
        s_cb[1][tid] = g_cb1[tid];
        s_pb2[tid]   = pre_b2[tid];
        s_bpo[tid]   = g_bpo[tid];
    }

    // ---- pre-stage: one-hot gather -> pre-hidden (sh_AB, stride 128) ----
    for (int e = tid; e < MROWS * 128; e += THREADS) {
        int r = e >> 7, c = e & 127;
        int n = nodeBase + r;
        float v = 0.f;
        if (n < BS * NN) {
            int g  = n >> 3;
            int s  = sources[n], t = targets[n], tp = types[n], d = diffs[n];
            int q  = question[g];
            v = pre_w1[s * 128 + c] + pre_w1[(8 + t) * 128 + c]
              + pre_w1[(16 + tp) * 128 + c] + pre_w1[(19 + d) * 128 + c]
              + pre_w1[(119 + q) * 128 + c] + pre_b1[c];
            v = fmaxf(v, 0.f);
        }
        sh_AB[r * 128 + c] = v;
    }
    // x = prehid @ pre_w2 + pre_b2 -> sh_hid (= h_0)
    {
        u64 acc[7][2] = {};
        gemmP<4>(acc, sh_AB, 128, (const float*)0, 0, pre_w2, sh_w, tid, ty, tx);
#pragma unroll
        for (int i = 0; i < 7; ++i)
#pragma unroll
            for (int j = 0; j < 2; ++j) {
                int r = ty + 8 * i, c = 2 * tx + 64 * j;
                float2 v = unpack2(acc[i][j]);
                v.x += s_pb2[c]; v.y += s_pb2[c + 1];
                *(float2*)&sh_hid[r * 128 + c] = v;
            }
    }
    // xc1 = x@node_w1[0:128] + bn1 ; xc0 = x@(W1x+W1h) + bn0  (both -> global)
    {
        u64 acc[7][2] = {};
        gemmP<4>(acc, sh_hid, 128, (const float*)0, 0, node_w1, sh_w, tid, ty, tx);
        float2 bn[2];
#pragma unroll
        for (int j = 0; j < 2; ++j) bn[j] = *(const float2*)&g_bn1[2 * tx + 64 * j];
#pragma unroll
        for (int i = 0; i < 7; ++i)
#pragma unroll
            for (int j = 0; j < 2; ++j) {
                int r = ty + 8 * i, c = 2 * tx + 64 * j;
                float2 v = unpack2(acc[i][j]);
                v.x += bn[j].x; v.y += bn[j].y;
                *(float2*)&g_xc1[(size_t)(nodeBase + r) * 128 + c] = v;
            }
    }
    {
        u64 acc[7][2] = {};
        gemmP<4>(acc, sh_hid, 128, (const float*)0, 0, g_Wsum, sh_w, tid, ty, tx);
        float2 bn[2];
#pragma unroll
        for (int j = 0; j < 2; ++j) bn[j] = *(const float2*)&g_bn0[2 * tx + 64 * j];
#pragma unroll
        for (int i = 0; i < 7; ++i)
#pragma unroll
            for (int j = 0; j < 2; ++j) {
                int r = ty + 8 * i, c = 2 * tx + 64 * j;
                float2 v = unpack2(acc[i][j]);
                v.x += bn[j].x; v.y += bn[j].y;
                *(float2*)&g_xc0[(size_t)(nodeBase + r) * 128 + c] = v;
            }
    }

    for (int s = 0; s < NSTEPS; ++s) {
        const float* wa = s ? g_WfA : msg_w1;
        const float* wb = s ? g_WfB : (msg_w1 + 128 * 128);

        // ---- P1: A = state@wa ; B = state@wb  -> sh_AB [A|B] ----
        {
            u64 acc[7][2] = {};
            gemmP<4>(acc, sh_hid, 128, (const float*)0, 0, wa, sh_w, tid, ty, tx);
#pragma unroll
            for (int i = 0; i < 7; ++i)
#pragma unroll
                for (int j = 0; j < 2; ++j)
                    *(float2*)&sh_AB[(ty + 8 * i) * 256 + 2 * tx + 64 * j] = unpack2(acc[i][j]);
        }
        {
            u64 acc[7][2] = {};
            gemmP<4>(acc, sh_hid, 128, (const float*)0, 0, wb, sh_w, tid, ty, tx);
#pragma unroll
            for (int i = 0; i < 7; ++i)
#pragma unroll
                for (int j = 0; j < 2; ++j)
                    *(float2*)&sh_AB[(ty + 8 * i) * 256 + 128 + 2 * tx + 64 * j] = unpack2(acc[i][j]);
        }
        __syncthreads();

        // ---- P2: S[i] = sum_{j!=i} relu(A[i]+cb+B[j]) in place over A ----
        {
            const float* cb = s_cb[s ? 1 : 0];
            for (int e = tid; e < MROWS * 64; e += THREADS) {
                int r = e >> 6, c = (e & 63) * 2;
                int gl8 = r & ~7;
                float2 a = *(const float2*)&sh_AB[r * 256 + c];
                a.x += cb[c]; a.y += cb[c + 1];
                float sx = 0.f, sy = 0.f;
#pragma unroll
                for (int j = 0; j < 8; ++j) {
                    float2 b = *(const float2*)&sh_AB[(gl8 + j) * 256 + 128 + c];
                    sx += fmaxf(a.x + b.x, 0.f);
                    sy += fmaxf(a.y + b.y, 0.f);
                }
                {
                    float2 b = *(const float2*)&sh_AB[r * 256 + 128 + c];
                    sx -= fmaxf(a.x + b.x, 0.f);
                    sy -= fmaxf(a.y + b.y, 0.f);
                }
                *(float2*)&sh_AB[r * 256 + c] = make_float2(sx, sy);
            }
        }

        // ---- P3: hid = relu([S | hid] @ [Wsn ; Wfh] + xc) ----
        {
            u64 acc[7][2] = {};
            if (s == 0)
                gemmP<4>(acc, sh_AB, 256, sh_hid, 128, g_W3, sh_w, tid, ty, tx);
            else
                gemmP<8>(acc, sh_AB, 256, sh_hid, 128, g_W3, sh_w, tid, ty, tx);
            __syncthreads();   // all K-reads of sh_hid complete
            const float* xc = s ? g_xc1 : g_xc0;
#pragma unroll
            for (int i = 0; i < 7; ++i) {
                int r = ty + 8 * i;
                size_t nb = (size_t)(nodeBase + r) * 128;
#pragma unroll
                for (int j = 0; j < 2; ++j) {
                    int c = 2 * tx + 64 * j;
                    float2 x2 = *(const float2*)&xc[nb + c];
                    float2 v = unpack2(acc[i][j]);
                    v.x = fmaxf(v.x + x2.x, 0.f);
                    v.y = fmaxf(v.y + x2.y, 0.f);
                    *(float2*)&sh_hid[r * 128 + c] = v;
                }
            }
        }
        __syncthreads();

        // ---- P5: pooled = per-graph row-sum(hid); o1 = relu(pooled@Wpo+bpo);
        //          logits = o1@out_w2 + out_b2 ----
        float* pooled = sh_w;
        float* o1     = sh_w + 1024;
        for (int e = tid; e < GPB * 128; e += THREADS) {
            int g = e >> 7, c = e & 127;
            float acc = 0.f;
#pragma unroll
            for (int i = 0; i < 8; ++i) acc += sh_hid[(g * 8 + i) * 128 + c];
            pooled[e] = acc;
        }
        __syncthreads();
        if (tid < 224) {
            int g = tid >> 5, c4 = (tid & 31) * 4;
            float4 a4 = *(const float4*)&s_bpo[c4];
            const float* pg = pooled + g * 128;
            const float* wp = g_Wpo + c4;
#pragma unroll 16
            for (int k = 0; k < 128; ++k) {
                float a = pg[k];
                float4 w = *(const float4*)&wp[k * 128];
                a4.x = fmaf(a, w.x, a4.x); a4.y = fmaf(a, w.y, a4.y);
                a4.z = fmaf(a, w.z, a4.z); a4.w = fmaf(a, w.w, a4.w);
            }
            a4.x = fmaxf(a4.x, 0.f); a4.y = fmaxf(a4.y, 0.f);
            a4.z = fmaxf(a4.z, 0.f); a4.w = fmaxf(a4.w, 0.f);
            *(float4*)&o1[g * 128 + c4] = a4;
        }
        __syncthreads();
        if (tid < 175) {
            int g = tid / 25, c4 = (tid - g * 25) * 4;
            float4 a4 = *(const float4*)&out_b2[c4];
            const float* og = o1 + g * 128;
            const float* w2 = out_w2 + c4;
#pragma unroll 16
            for (int k = 0; k < 128; ++k) {
                float a = og[k];
                float4 w = *(const float4*)&w2[k * 100];
                a4.x = fmaf(a, w.x, a4.x); a4.y = fmaf(a, w.y, a4.y);
                a4.z = fmaf(a, w.z, a4.z); a4.w = fmaf(a, w.w, a4.w);
            }
            int gg = graphBase + g;
            if (gg < BS)
                *(float4*)&out[((size_t)s * BS + gg) * 100 + c4] = a4;
        }
        // next P1's first __syncthreads covers sh_w reuse
    }
}

extern "C" void kernel_launch(void* const* d_in, const int* in_sizes, int n_in,
                              void* d_out, int out_size)
{
    (void)in_sizes; (void)n_in; (void)out_size;
    const int*   sources  = (const int*)d_in[0];
    const int*   targets  = (const int*)d_in[1];
    const int*   types    = (const int*)d_in[2];
    const int*   diffs    = (const int*)d_in[3];
    const int*   question = (const int*)d_in[4];
    const float* pre_w1   = (const float*)d_in[5];
    const float* pre_b1   = (const float*)d_in[6];
    const float* pre_w2   = (const float*)d_in[7];
    const float* pre_b2   = (const float*)d_in[8];
    const float* msg_w1   = (const float*)d_in[9];
    const float* msg_b1   = (const float*)d_in[10];
    const float* msg_w2   = (const float*)d_in[11];
    const float* msg_b2   = (const float*)d_in[12];
    const float* node_w1  = (const float*)d_in[13];
    const float* node_b1  = (const float*)d_in[14];
    const float* node_w2  = (const float*)d_in[15];
    const float* node_b2  = (const float*)d_in[16];
    const float* out_w1   = (const float*)d_in[17];
    const float* out_b1   = (const float*)d_in[18];
    const float* out_w2   = (const float*)d_in[19];
    const float* out_b2   = (const float*)d_in[20];
    float* out = (float*)d_out;

    cudaFuncSetAttribute(rrn_kernel, cudaFuncAttributeMaxDynamicSharedMemorySize,
                         SMEM_BYTES);

    fold_w<<<dim3(128, 6), 128>>>(msg_w1, msg_w2, node_w1, node_w2, out_w1);
    fold_b<<<1, 128>>>(msg_w1, msg_b1, msg_b2, node_w1, node_b1, node_b2,
                       out_w1, out_b1);
    rrn_kernel<<<NBLK, THREADS, SMEM_BYTES>>>(
        sources, targets, types, diffs, question,
        pre_w1, pre_b1, pre_w2, pre_b2,
        msg_w1, msg_b1, node_w1,
        out_w2, out_b2, out);
}